// round 13
// baseline (speedup 1.0000x reference)
#include <cuda_runtime.h>

// out[r,k] = 2^-11 * (WHT_2048(concat(x1,x2))[r,k])^2
// RZ phase cancels under |.|^2; real input -> real state.
//
// One row per 128-thread block, 16 blocks/SM.
//   phase1 regs: bits 0,1,6,7 -- 4x LDG.128, butterflies overlap loads,
//                4x STS.128 into padded layout
//   phase2 regs: bits 2..5    -- scalar LDS/STS in-place (verified pattern)
//   phase3 regs: bits 8,9,10 + i0 vector lane -- 8x LDS.64 (warp-contiguous,
//                conflict-free), 8x STG.64 fully coalesced
// Padded smem layout a(i) = i[10:7]*136 + i[6]*68 + i[5:0].

__global__ __launch_bounds__(128, 16)
void qfl_wht_kernel(const float* __restrict__ x1,
                    const float* __restrict__ x2,
                    float* __restrict__ out)
{
    __shared__ float s[2176];            // 8704 B/row

    const int t   = threadIdx.x;         // 0..127
    const int row = blockIdx.x;

    // ---- Phase 1: 4x LDG.128 ----------------------------------------------
    // i = (t>>4)*256 + (d>>1)*128 + (d&1)*64 + (t&15)*4 + j
    //   regs: i[1:0]=j (float4 lanes), i6=d&1, i7=d>>1
    //   thread: i[5:2]=t&15, i[10:8]=t>>4
    const float* srcb = ((t < 64) ? x1 : x2)
                      + (size_t)row * 1024 + ((t >> 4) & 3) * 256 + ((t & 15) << 2);
    float4 u[4];
#pragma unroll
    for (int d = 0; d < 4; ++d)
        u[d] = __ldcs((const float4*)(srcb + (d >> 1) * 128 + (d & 1) * 64));

    // butterflies on bits 0 and 1 (inside each float4; overlaps later loads)
#pragma unroll
    for (int d = 0; d < 4; ++d) {
        float a0 = u[d].x, a1 = u[d].y, a2 = u[d].z, a3 = u[d].w;
        float s0 = a0 + a1, d0 = a0 - a1;
        float s2 = a2 + a3, d2 = a2 - a3;
        u[d].x = s0 + s2;  u[d].z = s0 - s2;
        u[d].y = d0 + d2;  u[d].w = d0 - d2;
    }
    // butterfly on bit 6 (d&1): pairs (0,1),(2,3)
#pragma unroll
    for (int dd = 0; dd < 4; dd += 2) {
        float4 a = u[dd], b = u[dd + 1];
        u[dd]     = make_float4(a.x + b.x, a.y + b.y, a.z + b.z, a.w + b.w);
        u[dd + 1] = make_float4(a.x - b.x, a.y - b.y, a.z - b.z, a.w - b.w);
    }
    // butterfly on bit 7 (d>>1): pairs (0,2),(1,3)
#pragma unroll
    for (int dd = 0; dd < 2; ++dd) {
        float4 a = u[dd], b = u[dd + 2];
        u[dd]     = make_float4(a.x + b.x, a.y + b.y, a.z + b.z, a.w + b.w);
        u[dd + 2] = make_float4(a.x - b.x, a.y - b.y, a.z - b.z, a.w - b.w);
    }

    // STS.128: a(i) with i[10:7] = (t>>4)*2 + (d>>1), i6 = d&1
    {
        const int wb = ((t >> 4) << 1);
        const int lo = (t & 15) << 2;
#pragma unroll
        for (int d = 0; d < 4; ++d)
            *(float4*)&s[(wb + (d >> 1)) * 136 + (d & 1) * 68 + lo] = u[d];
    }
    __syncthreads();

    // ---- Phase 2: regs own q = i[5:2]; in-place (verified conflict-free) ---
    const int base2 = (t >> 3) * 136 + ((t >> 2) & 1) * 68 + (t & 3);
    float v[16];
#pragma unroll
    for (int q = 0; q < 16; ++q) v[q] = s[base2 + (q << 2)];

#pragma unroll
    for (int m = 1; m <= 8; m <<= 1) {
#pragma unroll
        for (int q = 0; q < 16; ++q) {
            if (!(q & m)) {
                float a = v[q], b = v[q | m];
                v[q]     = a + b;
                v[q | m] = a - b;
            }
        }
    }
#pragma unroll
    for (int q = 0; q < 16; ++q) s[base2 + (q << 2)] = v[q];
    __syncthreads();

    // ---- Phase 3: regs own r = i[10:8] (+ i0 vector lane) ------------------
    // thread bits: i[7:1] = t  (i7 = t>>6, i6 = (t>>5)&1, i[5:1] = t&31)
    // addr words = (2r + t>>6)*136 + ((t>>5)&1)*68 + (t&31)*2  -> per-warp
    // contiguous 256B per LDS.64 (t>>5 constant in warp): conflict-free.
    const int base3 = (t >> 6) * 136 + ((t >> 5) & 1) * 68 + ((t & 31) << 1);
    float2 w[8];
#pragma unroll
    for (int r = 0; r < 8; ++r)
        w[r] = *(const float2*)&s[(r << 1) * 136 + base3];

    // butterflies on bits 8,9,10 (r index)
#pragma unroll
    for (int m = 1; m <= 4; m <<= 1) {
#pragma unroll
        for (int r = 0; r < 8; ++r) {
            if (!(r & m)) {
                float2 a = w[r], b = w[r | m];
                w[r]     = make_float2(a.x + b.x, a.y + b.y);
                w[r | m] = make_float2(a.x - b.x, a.y - b.y);
            }
        }
    }

    // ---- Square, scale, coalesced STG.64 (256B contiguous per warp) -------
    const float sc = 1.0f / 2048.0f;
    float* o = out + (size_t)row * 2048 + (t << 1);   // + r*256 + i0
#pragma unroll
    for (int r = 0; r < 8; ++r) {
        float2 z = w[r];
        z.x = z.x * z.x * sc;
        z.y = z.y * z.y * sc;
        *(float2*)&o[r << 8] = z;
    }
}

extern "C" void kernel_launch(void* const* d_in, const int* in_sizes, int n_in,
                              void* d_out, int out_size)
{
    const float* x1 = (const float*)d_in[0];   // (8192, 1024) f32
    const float* x2 = (const float*)d_in[1];   // (8192, 1024) f32
    float* out = (float*)d_out;                // (8192, 2048) f32

    const int rows = in_sizes[0] / 1024;       // 8192
    qfl_wht_kernel<<<rows, 128>>>(x1, x2, out);
}